// round 3
// baseline (speedup 1.0000x reference)
#include <cuda_runtime.h>
#include <math.h>

#define Bn  8
#define Tn  1024
#define Dn  1024
#define Hn  16
#define HDn 64
#define FFn 4096
#define BT  (Bn*Tn)

// ---- scratch (static device globals; no allocation anywhere) ----
__device__ float g_h  [BT*Dn];        // LN1 output
__device__ float g_q  [Bn*Hn*Tn*HDn];
__device__ float g_k  [Bn*Hn*Tn*HDn];
__device__ float g_v  [Bn*Hn*Tn*HDn];
__device__ float g_ctx[BT*Dn];        // attention context, (b,t,h*64+e)
__device__ float g_x1 [BT*Dn];        // x + attn_out
__device__ float g_h2 [BT*Dn];        // LN2 output
__device__ float g_ff [BT*FFn];       // gelu(h2@W1+b1)

// ======================= LayerNorm =======================
__global__ void __launch_bounds__(256) ln_kernel(const float* __restrict__ x,
                                                 const float* __restrict__ gma,
                                                 const float* __restrict__ bta,
                                                 float* __restrict__ out)
{
    int row = blockIdx.x;
    int tid = threadIdx.x;
    const float4 v = *(const float4*)(x + row*Dn + tid*4);
    float s = v.x + v.y + v.z + v.w;
    float q = v.x*v.x + v.y*v.y + v.z*v.z + v.w*v.w;
    #pragma unroll
    for (int o = 16; o > 0; o >>= 1) {
        s += __shfl_xor_sync(0xffffffffu, s, o);
        q += __shfl_xor_sync(0xffffffffu, q, o);
    }
    __shared__ float ss[8], sq[8];
    __shared__ float s_mu, s_rs;
    int w = tid >> 5;
    if ((tid & 31) == 0) { ss[w] = s; sq[w] = q; }
    __syncthreads();
    if (tid == 0) {
        float ts = 0.f, tq = 0.f;
        #pragma unroll
        for (int i = 0; i < 8; i++) { ts += ss[i]; tq += sq[i]; }
        float mu  = ts * (1.0f/Dn);
        float var = tq * (1.0f/Dn) - mu*mu;
        s_mu = mu;
        s_rs = rsqrtf(var + 1e-5f);
    }
    __syncthreads();
    float mu = s_mu, rs = s_rs;
    const float4 g4 = *(const float4*)(gma + tid*4);
    const float4 b4 = *(const float4*)(bta + tid*4);
    float4 o;
    o.x = (v.x - mu)*rs*g4.x + b4.x;
    o.y = (v.y - mu)*rs*g4.y + b4.y;
    o.z = (v.z - mu)*rs*g4.z + b4.z;
    o.w = (v.w - mu)*rs*g4.w + b4.w;
    *(float4*)(out + row*Dn + tid*4) = o;
}

// ======================= SGEMM 128x128, BK=8, 8x8/thread, double-buffered =======================
// C[M,N] = A[M,K] @ B[K,N] + bias ; optional exact GELU ; optional +res
__global__ void __launch_bounds__(256) sgemm128_kernel(
    const float* __restrict__ A, const float* __restrict__ Bm,
    const float* __restrict__ bias, const float* __restrict__ res,
    float* __restrict__ C, int M, int N, int K, int gelu)
{
    __shared__ float As[2][8][132];   // transposed [k][row], pitch 132 (conflict-free stores)
    __shared__ float Bs[2][8][128];   // natural    [k][col]
    const int tid = threadIdx.x;
    const int tx = tid & 15, ty = tid >> 4;
    const int row0 = blockIdx.y << 7;
    const int col0 = blockIdx.x << 7;
    const int a_row = tid >> 1, a_k = (tid & 1) << 2;
    const int b_row = tid >> 5, b_col = (tid & 31) << 2;

    const float* Ap = A + (row0 + a_row) * K + a_k;
    const float* Bp = Bm + b_row * N + col0 + b_col;

    float acc[8][8];
    #pragma unroll
    for (int i = 0; i < 8; i++)
        #pragma unroll
        for (int j = 0; j < 8; j++) acc[i][j] = 0.f;

    // prologue: tile 0
    {
        float4 a = *(const float4*)(Ap);
        float4 b = *(const float4*)(Bp);
        As[0][a_k+0][a_row] = a.x; As[0][a_k+1][a_row] = a.y;
        As[0][a_k+2][a_row] = a.z; As[0][a_k+3][a_row] = a.w;
        *(float4*)&Bs[0][b_row][b_col] = b;
    }
    __syncthreads();

    const int ntiles = K >> 3;
    for (int t = 0; t < ntiles; t++) {
        const int cur = t & 1;
        float4 an, bn;
        const bool more = (t + 1 < ntiles);
        if (more) {
            an = *(const float4*)(Ap + (t+1)*8);
            bn = *(const float4*)(Bp + (size_t)(t+1)*8*N);
        }
        #pragma unroll
        for (int kk = 0; kk < 8; kk++) {
            float4 a0 = *(const float4*)&As[cur][kk][ty*8];
            float4 a1 = *(const float4*)&As[cur][kk][ty*8 + 4];
            float4 b0 = *(const float4*)&Bs[cur][kk][tx*8];
            float4 b1 = *(const float4*)&Bs[cur][kk][tx*8 + 4];
            float av[8] = {a0.x,a0.y,a0.z,a0.w,a1.x,a1.y,a1.z,a1.w};
            float bv[8] = {b0.x,b0.y,b0.z,b0.w,b1.x,b1.y,b1.z,b1.w};
            #pragma unroll
            for (int i = 0; i < 8; i++)
                #pragma unroll
                for (int j = 0; j < 8; j++) acc[i][j] += av[i]*bv[j];
        }
        if (more) {
            const int nxt = cur ^ 1;
            As[nxt][a_k+0][a_row] = an.x; As[nxt][a_k+1][a_row] = an.y;
            As[nxt][a_k+2][a_row] = an.z; As[nxt][a_k+3][a_row] = an.w;
            *(float4*)&Bs[nxt][b_row][b_col] = bn;
            __syncthreads();
        }
    }

    const int cc = col0 + (tx << 3);
    const float4 bv0 = *(const float4*)(bias + cc);
    const float4 bv1 = *(const float4*)(bias + cc + 4);
    #pragma unroll
    for (int i = 0; i < 8; i++) {
        const int r = row0 + ty*8 + i;
        float o[8];
        o[0]=acc[i][0]+bv0.x; o[1]=acc[i][1]+bv0.y; o[2]=acc[i][2]+bv0.z; o[3]=acc[i][3]+bv0.w;
        o[4]=acc[i][4]+bv1.x; o[5]=acc[i][5]+bv1.y; o[6]=acc[i][6]+bv1.z; o[7]=acc[i][7]+bv1.w;
        if (gelu) {
            #pragma unroll
            for (int j = 0; j < 8; j++)
                o[j] = 0.5f*o[j]*(1.0f + erff(o[j]*0.70710678118654752f));
        }
        if (res) {
            float4 r0 = *(const float4*)(res + (size_t)r*N + cc);
            float4 r1 = *(const float4*)(res + (size_t)r*N + cc + 4);
            o[0]+=r0.x; o[1]+=r0.y; o[2]+=r0.z; o[3]+=r0.w;
            o[4]+=r1.x; o[5]+=r1.y; o[6]+=r1.z; o[7]+=r1.w;
        }
        *(float4*)(C + (size_t)r*N + cc)     = make_float4(o[0],o[1],o[2],o[3]);
        *(float4*)(C + (size_t)r*N + cc + 4) = make_float4(o[4],o[5],o[6],o[7]);
    }
}

// ======================= fused QKV projection (128x128 tiles, head-blocked B) =======================
// grid.x = 24: proj = bx>>3, col-tile = bx&7 (128 cols spanning 2 heads). grid.y = 64 row tiles.
// Reads g_h; writes g_q/g_k/g_v in (B,H,T,HD) layout.
__global__ void __launch_bounds__(256) qkv128_kernel(
    const float* __restrict__ Wq, const float* __restrict__ Wk, const float* __restrict__ Wv,
    const float* __restrict__ bq, const float* __restrict__ bk, const float* __restrict__ bv)
{
    __shared__ float As[2][8][132];
    __shared__ float Bs[2][8][128];
    const int proj = blockIdx.x >> 3;
    const int col0 = (blockIdx.x & 7) << 7;          // proj-local column tile
    const float* W    = (proj == 0 ? Wq : (proj == 1 ? Wk : Wv));
    const float* bias = (proj == 0 ? bq : (proj == 1 ? bk : bv));
    float* outp       = (proj == 0 ? g_q : (proj == 1 ? g_k : g_v));

    const int tid = threadIdx.x;
    const int tx = tid & 15, ty = tid >> 4;
    const int row0 = blockIdx.y << 7;
    const int a_row = tid >> 1, a_k = (tid & 1) << 2;
    const int b_row = tid >> 5, b_col = (tid & 31) << 2;

    // virtual B[d, c] with c = col0 + b_col -> W[h, d, e], h=c>>6, e=c&63
    const int gcol = col0 + b_col;
    const float* Ap = g_h + (row0 + a_row) * Dn + a_k;
    const float* Bp = W + (gcol >> 6) * (Dn*HDn) + b_row * HDn + (gcol & 63);

    float acc[8][8];
    #pragma unroll
    for (int i = 0; i < 8; i++)
        #pragma unroll
        for (int j = 0; j < 8; j++) acc[i][j] = 0.f;

    {
        float4 a = *(const float4*)(Ap);
        float4 b = *(const float4*)(Bp);
        As[0][a_k+0][a_row] = a.x; As[0][a_k+1][a_row] = a.y;
        As[0][a_k+2][a_row] = a.z; As[0][a_k+3][a_row] = a.w;
        *(float4*)&Bs[0][b_row][b_col] = b;
    }
    __syncthreads();

    const int ntiles = Dn >> 3;   // 128
    for (int t = 0; t < ntiles; t++) {
        const int cur = t & 1;
        float4 an, bn;
        const bool more = (t + 1 < ntiles);
        if (more) {
            an = *(const float4*)(Ap + (t+1)*8);
            bn = *(const float4*)(Bp + (t+1)*8*HDn);
        }
        #pragma unroll
        for (int kk = 0; kk < 8; kk++) {
            float4 a0 = *(const float4*)&As[cur][kk][ty*8];
            float4 a1 = *(const float4*)&As[cur][kk][ty*8 + 4];
            float4 b0 = *(const float4*)&Bs[cur][kk][tx*8];
            float4 b1 = *(const float4*)&Bs[cur][kk][tx*8 + 4];
            float av[8] = {a0.x,a0.y,a0.z,a0.w,a1.x,a1.y,a1.z,a1.w};
            float bv[8] = {b0.x,b0.y,b0.z,b0.w,b1.x,b1.y,b1.z,b1.w};
            #pragma unroll
            for (int i = 0; i < 8; i++)
                #pragma unroll
                for (int j = 0; j < 8; j++) acc[i][j] += av[i]*bv[j];
        }
        if (more) {
            const int nxt = cur ^ 1;
            As[nxt][a_k+0][a_row] = an.x; As[nxt][a_k+1][a_row] = an.y;
            As[nxt][a_k+2][a_row] = an.z; As[nxt][a_k+3][a_row] = an.w;
            *(float4*)&Bs[nxt][b_row][b_col] = bn;
            __syncthreads();
        }
    }

    // epilogue: cols c = col0 + tx*8 .. +7, all within one head (tx*8 & 63 <= 56)
    const int c = col0 + (tx << 3);
    const int h = c >> 6, e = c & 63;
    const float4 bv0 = *(const float4*)(bias + c);       // bias is contiguous (H,HD) = 1024 floats
    const float4 bv1 = *(const float4*)(bias + c + 4);
    #pragma unroll
    for (int i = 0; i < 8; i++) {
        const int r = row0 + ty*8 + i;
        const int b = r >> 10, tt = r & 1023;
        float* op = outp + (((size_t)(b*Hn + h)*Tn + tt)*HDn + e);
        *(float4*)(op)     = make_float4(acc[i][0]+bv0.x, acc[i][1]+bv0.y, acc[i][2]+bv0.z, acc[i][3]+bv0.w);
        *(float4*)(op + 4) = make_float4(acc[i][4]+bv1.x, acc[i][5]+bv1.y, acc[i][6]+bv1.z, acc[i][7]+bv1.w);
    }
}

// ======================= flash attention (fp32, Br=Bc=64) =======================
// grid: (T/64, B*H). smem: Qs[e][r] 16KB, Ks[e][c] 16KB, Vs[c][d] 16KB, Ps[r][68] 17KB
__global__ void __launch_bounds__(256) attn_kernel()
{
    extern __shared__ float sm[];
    float* Qs = sm;            // transposed [e*64 + r]
    float* Ks = sm + 4096;     // transposed [e*64 + c]
    float* Vs = sm + 8192;     // natural    [c*64 + d]
    float* Ps = sm + 12288;    // padded     [r*68 + c]
    const int tid = threadIdx.x;
    const int tx = tid & 15, ty = tid >> 4;
    const int t0 = blockIdx.x << 6;
    const int bh = blockIdx.y;
    const float* qp = g_q + (size_t)bh * (Tn*HDn);
    const float* kp = g_k + (size_t)bh * (Tn*HDn);
    const float* vp = g_v + (size_t)bh * (Tn*HDn);

    #pragma unroll
    for (int rep = 0; rep < 4; rep++) {
        int fi = tid + rep*256;
        int r = fi >> 4;
        int e = (fi & 15) << 2;
        float4 v = *(const float4*)(qp + (t0 + r)*HDn + e);
        Qs[(e+0)*64 + r] = v.x*0.125f;
        Qs[(e+1)*64 + r] = v.y*0.125f;
        Qs[(e+2)*64 + r] = v.z*0.125f;
        Qs[(e+3)*64 + r] = v.w*0.125f;
    }

    float m_i[4], l_i[4], acc[4][4];
    #pragma unroll
    for (int i = 0; i < 4; i++) {
        m_i[i] = -1e30f; l_i[i] = 0.f;
        #pragma unroll
        for (int j = 0; j < 4; j++) acc[i][j] = 0.f;
    }

    for (int kb = 0; kb < Tn; kb += 64) {
        __syncthreads();   // prior iter done with Ks/Vs/Ps; also fences Qs on iter 0
        #pragma unroll
        for (int rep = 0; rep < 4; rep++) {
            int fi = tid + rep*256;
            int r = fi >> 4;
            int e = (fi & 15) << 2;
            float4 kv = *(const float4*)(kp + (kb + r)*HDn + e);
            Ks[(e+0)*64 + r] = kv.x;
            Ks[(e+1)*64 + r] = kv.y;
            Ks[(e+2)*64 + r] = kv.z;
            Ks[(e+3)*64 + r] = kv.w;
            float4 vv = *(const float4*)(vp + (kb + r)*HDn + e);
            *(float4*)&Vs[r*64 + e] = vv;
        }
        __syncthreads();

        float s[4][4];
        #pragma unroll
        for (int i = 0; i < 4; i++)
            #pragma unroll
            for (int j = 0; j < 4; j++) s[i][j] = 0.f;
        #pragma unroll
        for (int e = 0; e < 64; e++) {
            float4 q4 = *(const float4*)&Qs[e*64 + (ty<<2)];
            float4 k4 = *(const float4*)&Ks[e*64 + (tx<<2)];
            float qa[4] = {q4.x,q4.y,q4.z,q4.w};
            float ka4[4] = {k4.x,k4.y,k4.z,k4.w};
            #pragma unroll
            for (int i = 0; i < 4; i++)
                #pragma unroll
                for (int j = 0; j < 4; j++) s[i][j] += qa[i]*ka4[j];
        }

        #pragma unroll
        for (int i = 0; i < 4; i++) {
            float mx = fmaxf(fmaxf(s[i][0], s[i][1]), fmaxf(s[i][2], s[i][3]));
            mx = fmaxf(mx, __shfl_xor_sync(0xffffffffu, mx, 1));
            mx = fmaxf(mx, __shfl_xor_sync(0xffffffffu, mx, 2));
            mx = fmaxf(mx, __shfl_xor_sync(0xffffffffu, mx, 4));
            mx = fmaxf(mx, __shfl_xor_sync(0xffffffffu, mx, 8));
            float mn = fmaxf(m_i[i], mx);
            float alpha = __expf(m_i[i] - mn);
            m_i[i] = mn;
            float rs = 0.f;
            #pragma unroll
            for (int j = 0; j < 4; j++) { s[i][j] = __expf(s[i][j] - mn); rs += s[i][j]; }
            rs += __shfl_xor_sync(0xffffffffu, rs, 1);
            rs += __shfl_xor_sync(0xffffffffu, rs, 2);
            rs += __shfl_xor_sync(0xffffffffu, rs, 4);
            rs += __shfl_xor_sync(0xffffffffu, rs, 8);
            l_i[i] = l_i[i]*alpha + rs;
            #pragma unroll
            for (int j = 0; j < 4; j++) acc[i][j] *= alpha;
            *(float4*)&Ps[((ty<<2)+i)*68 + (tx<<2)] = make_float4(s[i][0], s[i][1], s[i][2], s[i][3]);
        }
        __syncthreads();

        // PV: process 4 columns per step, vectorized P loads (8 LDS.128 / 64 FFMA)
        #pragma unroll
        for (int c = 0; c < 64; c += 4) {
            float4 v0 = *(const float4*)&Vs[(c+0)*64 + (tx<<2)];
            float4 v1 = *(const float4*)&Vs[(c+1)*64 + (tx<<2)];
            float4 v2 = *(const float4*)&Vs[(c+2)*64 + (tx<<2)];
            float4 v3 = *(const float4*)&Vs[(c+3)*64 + (tx<<2)];
            #pragma unroll
            for (int i = 0; i < 4; i++) {
                float4 p4 = *(const float4*)&Ps[((ty<<2)+i)*68 + c];
                acc[i][0] += p4.x*v0.x; acc[i][1] += p4.x*v0.y; acc[i][2] += p4.x*v0.z; acc[i][3] += p4.x*v0.w;
                acc[i][0] += p4.y*v1.x; acc[i][1] += p4.y*v1.y; acc[i][2] += p4.y*v1.z; acc[i][3] += p4.y*v1.w;
                acc[i][0] += p4.z*v2.x; acc[i][1] += p4.z*v2.y; acc[i][2] += p4.z*v2.z; acc[i][3] += p4.z*v2.w;
                acc[i][0] += p4.w*v3.x; acc[i][1] += p4.w*v3.y; acc[i][2] += p4.w*v3.z; acc[i][3] += p4.w*v3.w;
            }
        }
    }

    const int b = bh >> 4, h = bh & 15;
    #pragma unroll
    for (int i = 0; i < 4; i++) {
        float inv = 1.0f / l_i[i];
        int t = t0 + (ty<<2) + i;
        float4 o = make_float4(acc[i][0]*inv, acc[i][1]*inv, acc[i][2]*inv, acc[i][3]*inv);
        *(float4*)&g_ctx[((size_t)(b*Tn + t))*Dn + h*HDn + (tx<<2)] = o;
    }
}

// ======================= launch =======================
extern "C" void kernel_launch(void* const* d_in, const int* in_sizes, int n_in,
                              void* d_out, int out_size)
{
    const float* x    = (const float*)d_in[0];
    const float* ln1g = (const float*)d_in[1];
    const float* ln1b = (const float*)d_in[2];
    const float* ln2g = (const float*)d_in[3];
    const float* ln2b = (const float*)d_in[4];
    const float* Wq   = (const float*)d_in[5];
    const float* bq   = (const float*)d_in[6];
    const float* Wk   = (const float*)d_in[7];
    const float* bk   = (const float*)d_in[8];
    const float* Wv   = (const float*)d_in[9];
    const float* bv   = (const float*)d_in[10];
    const float* Wo   = (const float*)d_in[11];
    const float* bo   = (const float*)d_in[12];
    const float* W1   = (const float*)d_in[13];
    const float* b1   = (const float*)d_in[14];
    const float* W2   = (const float*)d_in[15];
    const float* b2   = (const float*)d_in[16];
    float* out = (float*)d_out;

    float *p_h, *p_x1, *p_h2, *p_ctx, *p_ff;
    cudaGetSymbolAddress((void**)&p_h,   g_h);
    cudaGetSymbolAddress((void**)&p_x1,  g_x1);
    cudaGetSymbolAddress((void**)&p_h2,  g_h2);
    cudaGetSymbolAddress((void**)&p_ctx, g_ctx);
    cudaGetSymbolAddress((void**)&p_ff,  g_ff);

    cudaFuncSetAttribute(attn_kernel, cudaFuncAttributeMaxDynamicSharedMemorySize, 66560);

    // h = LN1(x)
    ln_kernel<<<BT, 256>>>(x, ln1g, ln1b, p_h);
    // q,k,v = h @ W{q,k,v} + b  (per head), one fused launch
    qkv128_kernel<<<dim3(24, BT/128), 256>>>(Wq, Wk, Wv, bq, bk, bv);
    // ctx = softmax(q k^T / 8) v   -> (b,t,h*64+e)
    attn_kernel<<<dim3(Tn/64, Bn*Hn), 256, 66560>>>();
    // x1 = x + ctx @ Wo + bo
    sgemm128_kernel<<<dim3(Dn/128, BT/128), 256>>>(p_ctx, Wo, bo, x, p_x1, BT, Dn, Dn, 0);
    // h2 = LN2(x1)
    ln_kernel<<<BT, 256>>>(p_x1, ln2g, ln2b, p_h2);
    // ff = gelu(h2 @ W1 + b1)
    sgemm128_kernel<<<dim3(FFn/128, BT/128), 256>>>(p_h2, W1, b1, nullptr, p_ff, BT, FFn, Dn, 1);
    // out = x1 + ff @ W2 + b2
    sgemm128_kernel<<<dim3(Dn/128, BT/128), 256>>>(p_ff, W2, b2, p_x1, out, BT, Dn, FFn, 0);
}

// round 9
// speedup vs baseline: 1.1113x; 1.1113x over previous
#include <cuda_runtime.h>
#include <math.h>

#define Bn  8
#define Tn  1024
#define Dn  1024
#define Hn  16
#define HDn 64
#define FFn 4096
#define BT  (Bn*Tn)

// ---- scratch (static device globals; no allocation anywhere) ----
__device__ float g_h  [BT*Dn];        // LN1 output
__device__ float g_q  [Bn*Hn*Tn*HDn];
__device__ float g_k  [Bn*Hn*Tn*HDn];
__device__ float g_v  [Bn*Hn*Tn*HDn];
__device__ float g_ctx[BT*Dn];        // attention context, (b,t,h*64+e)
__device__ float g_x1 [BT*Dn];        // x + attn_out
__device__ float g_h2 [BT*Dn];        // LN2 output
__device__ float g_ff [BT*FFn];       // gelu(h2@W1+b1)

// ======================= LayerNorm =======================
__global__ void __launch_bounds__(256) ln_kernel(const float* __restrict__ x,
                                                 const float* __restrict__ gma,
                                                 const float* __restrict__ bta,
                                                 float* __restrict__ out)
{
    int row = blockIdx.x;
    int tid = threadIdx.x;
    const float4 v = *(const float4*)(x + row*Dn + tid*4);
    float s = v.x + v.y + v.z + v.w;
    float q = v.x*v.x + v.y*v.y + v.z*v.z + v.w*v.w;
    #pragma unroll
    for (int o = 16; o > 0; o >>= 1) {
        s += __shfl_xor_sync(0xffffffffu, s, o);
        q += __shfl_xor_sync(0xffffffffu, q, o);
    }
    __shared__ float ss[8], sq[8];
    __shared__ float s_mu, s_rs;
    int w = tid >> 5;
    if ((tid & 31) == 0) { ss[w] = s; sq[w] = q; }
    __syncthreads();
    if (tid == 0) {
        float ts = 0.f, tq = 0.f;
        #pragma unroll
        for (int i = 0; i < 8; i++) { ts += ss[i]; tq += sq[i]; }
        float mu  = ts * (1.0f/Dn);
        float var = tq * (1.0f/Dn) - mu*mu;
        s_mu = mu;
        s_rs = rsqrtf(var + 1e-5f);
    }
    __syncthreads();
    float mu = s_mu, rs = s_rs;
    const float4 g4 = *(const float4*)(gma + tid*4);
    const float4 b4 = *(const float4*)(bta + tid*4);
    float4 o;
    o.x = (v.x - mu)*rs*g4.x + b4.x;
    o.y = (v.y - mu)*rs*g4.y + b4.y;
    o.z = (v.z - mu)*rs*g4.z + b4.z;
    o.w = (v.w - mu)*rs*g4.w + b4.w;
    *(float4*)(out + row*Dn + tid*4) = o;
}

// ======================= SGEMM 128x128, BK=8, 8x8/thread, double-buffered =======================
// C[M,N] = A[M,K] @ B[K,N] + bias ; optional exact GELU ; optional +res
// __launch_bounds__(256,2): cap regs at 128 so 2 CTAs co-reside per SM (16 warps).
__global__ void __launch_bounds__(256, 2) sgemm128_kernel(
    const float* __restrict__ A, const float* __restrict__ Bm,
    const float* __restrict__ bias, const float* __restrict__ res,
    float* __restrict__ C, int M, int N, int K, int gelu)
{
    __shared__ float As[2][8][132];   // transposed [k][row], pitch 132 (conflict-free stores)
    __shared__ float Bs[2][8][128];   // natural    [k][col]
    const int tid = threadIdx.x;
    const int tx = tid & 15, ty = tid >> 4;
    const int row0 = blockIdx.y << 7;
    const int col0 = blockIdx.x << 7;
    const int a_row = tid >> 1, a_k = (tid & 1) << 2;
    const int b_row = tid >> 5, b_col = (tid & 31) << 2;

    const float* Ap = A + (row0 + a_row) * K + a_k;
    const float* Bp = Bm + b_row * N + col0 + b_col;

    float acc[8][8];
    #pragma unroll
    for (int i = 0; i < 8; i++)
        #pragma unroll
        for (int j = 0; j < 8; j++) acc[i][j] = 0.f;

    // prologue: tile 0
    {
        float4 a = *(const float4*)(Ap);
        float4 b = *(const float4*)(Bp);
        As[0][a_k+0][a_row] = a.x; As[0][a_k+1][a_row] = a.y;
        As[0][a_k+2][a_row] = a.z; As[0][a_k+3][a_row] = a.w;
        *(float4*)&Bs[0][b_row][b_col] = b;
    }
    __syncthreads();

    const int ntiles = K >> 3;
    for (int t = 0; t < ntiles; t++) {
        const int cur = t & 1;
        float4 an, bn;
        const bool more = (t + 1 < ntiles);
        if (more) {
            an = *(const float4*)(Ap + (t+1)*8);
            bn = *(const float4*)(Bp + (size_t)(t+1)*8*N);
        }
        #pragma unroll
        for (int kk = 0; kk < 8; kk++) {
            float4 a0 = *(const float4*)&As[cur][kk][ty*8];
            float4 a1 = *(const float4*)&As[cur][kk][ty*8 + 4];
            float4 b0 = *(const float4*)&Bs[cur][kk][tx*8];
            float4 b1 = *(const float4*)&Bs[cur][kk][tx*8 + 4];
            float av[8] = {a0.x,a0.y,a0.z,a0.w,a1.x,a1.y,a1.z,a1.w};
            float bv[8] = {b0.x,b0.y,b0.z,b0.w,b1.x,b1.y,b1.z,b1.w};
            #pragma unroll
            for (int i = 0; i < 8; i++)
                #pragma unroll
                for (int j = 0; j < 8; j++) acc[i][j] += av[i]*bv[j];
        }
        if (more) {
            const int nxt = cur ^ 1;
            As[nxt][a_k+0][a_row] = an.x; As[nxt][a_k+1][a_row] = an.y;
            As[nxt][a_k+2][a_row] = an.z; As[nxt][a_k+3][a_row] = an.w;
            *(float4*)&Bs[nxt][b_row][b_col] = bn;
            __syncthreads();
        }
    }

    const int cc = col0 + (tx << 3);
    const float4 bv0 = *(const float4*)(bias + cc);
    const float4 bv1 = *(const float4*)(bias + cc + 4);
    #pragma unroll
    for (int i = 0; i < 8; i++) {
        const int r = row0 + ty*8 + i;
        float o[8];
        o[0]=acc[i][0]+bv0.x; o[1]=acc[i][1]+bv0.y; o[2]=acc[i][2]+bv0.z; o[3]=acc[i][3]+bv0.w;
        o[4]=acc[i][4]+bv1.x; o[5]=acc[i][5]+bv1.y; o[6]=acc[i][6]+bv1.z; o[7]=acc[i][7]+bv1.w;
        if (gelu) {
            #pragma unroll
            for (int j = 0; j < 8; j++)
                o[j] = 0.5f*o[j]*(1.0f + erff(o[j]*0.70710678118654752f));
        }
        if (res) {
            float4 r0 = *(const float4*)(res + (size_t)r*N + cc);
            float4 r1 = *(const float4*)(res + (size_t)r*N + cc + 4);
            o[0]+=r0.x; o[1]+=r0.y; o[2]+=r0.z; o[3]+=r0.w;
            o[4]+=r1.x; o[5]+=r1.y; o[6]+=r1.z; o[7]+=r1.w;
        }
        *(float4*)(C + (size_t)r*N + cc)     = make_float4(o[0],o[1],o[2],o[3]);
        *(float4*)(C + (size_t)r*N + cc + 4) = make_float4(o[4],o[5],o[6],o[7]);
    }
}

// ======================= fused QKV projection (128x128 tiles, head-blocked B) =======================
// grid.x = 24: proj = bx>>3, col-tile = bx&7 (128 cols spanning 2 heads). grid.y = 64 row tiles.
// Reads g_h; writes g_q/g_k/g_v in (B,H,T,HD) layout.
__global__ void __launch_bounds__(256, 2) qkv128_kernel(
    const float* __restrict__ Wq, const float* __restrict__ Wk, const float* __restrict__ Wv,
    const float* __restrict__ bq, const float* __restrict__ bk, const float* __restrict__ bv)
{
    __shared__ float As[2][8][132];
    __shared__ float Bs[2][8][128];
    const int proj = blockIdx.x >> 3;
    const int col0 = (blockIdx.x & 7) << 7;          // proj-local column tile
    const float* W    = (proj == 0 ? Wq : (proj == 1 ? Wk : Wv));
    const float* bias = (proj == 0 ? bq : (proj == 1 ? bk : bv));
    float* outp       = (proj == 0 ? g_q : (proj == 1 ? g_k : g_v));

    const int tid = threadIdx.x;
    const int tx = tid & 15, ty = tid >> 4;
    const int row0 = blockIdx.y << 7;
    const int a_row = tid >> 1, a_k = (tid & 1) << 2;
    const int b_row = tid >> 5, b_col = (tid & 31) << 2;

    // virtual B[d, c] with c = col0 + b_col -> W[h, d, e], h=c>>6, e=c&63
    const int gcol = col0 + b_col;
    const float* Ap = g_h + (row0 + a_row) * Dn + a_k;
    const float* Bp = W + (gcol >> 6) * (Dn*HDn) + b_row * HDn + (gcol & 63);

    float acc[8][8];
    #pragma unroll
    for (int i = 0; i < 8; i++)
        #pragma unroll
        for (int j = 0; j < 8; j++) acc[i][j] = 0.f;

    {
        float4 a = *(const float4*)(Ap);
        float4 b = *(const float4*)(Bp);
        As[0][a_k+0][a_row] = a.x; As[0][a_k+1][a_row] = a.y;
        As[0][a_k+2][a_row] = a.z; As[0][a_k+3][a_row] = a.w;
        *(float4*)&Bs[0][b_row][b_col] = b;
    }
    __syncthreads();

    const int ntiles = Dn >> 3;   // 128
    for (int t = 0; t < ntiles; t++) {
        const int cur = t & 1;
        float4 an, bn;
        const bool more = (t + 1 < ntiles);
        if (more) {
            an = *(const float4*)(Ap + (t+1)*8);
            bn = *(const float4*)(Bp + (t+1)*8*HDn);
        }
        #pragma unroll
        for (int kk = 0; kk < 8; kk++) {
            float4 a0 = *(const float4*)&As[cur][kk][ty*8];
            float4 a1 = *(const float4*)&As[cur][kk][ty*8 + 4];
            float4 b0 = *(const float4*)&Bs[cur][kk][tx*8];
            float4 b1 = *(const float4*)&Bs[cur][kk][tx*8 + 4];
            float av[8] = {a0.x,a0.y,a0.z,a0.w,a1.x,a1.y,a1.z,a1.w};
            float bv[8] = {b0.x,b0.y,b0.z,b0.w,b1.x,b1.y,b1.z,b1.w};
            #pragma unroll
            for (int i = 0; i < 8; i++)
                #pragma unroll
                for (int j = 0; j < 8; j++) acc[i][j] += av[i]*bv[j];
        }
        if (more) {
            const int nxt = cur ^ 1;
            As[nxt][a_k+0][a_row] = an.x; As[nxt][a_k+1][a_row] = an.y;
            As[nxt][a_k+2][a_row] = an.z; As[nxt][a_k+3][a_row] = an.w;
            *(float4*)&Bs[nxt][b_row][b_col] = bn;
            __syncthreads();
        }
    }

    // epilogue: cols c = col0 + tx*8 .. +7, all within one head (tx*8 & 63 <= 56)
    const int c = col0 + (tx << 3);
    const int h = c >> 6, e = c & 63;
    const float4 bv0 = *(const float4*)(bias + c);       // bias is contiguous (H,HD) = 1024 floats
    const float4 bv1 = *(const float4*)(bias + c + 4);
    #pragma unroll
    for (int i = 0; i < 8; i++) {
        const int r = row0 + ty*8 + i;
        const int b = r >> 10, tt = r & 1023;
        float* op = outp + (((size_t)(b*Hn + h)*Tn + tt)*HDn + e);
        *(float4*)(op)     = make_float4(acc[i][0]+bv0.x, acc[i][1]+bv0.y, acc[i][2]+bv0.z, acc[i][3]+bv0.w);
        *(float4*)(op + 4) = make_float4(acc[i][4]+bv1.x, acc[i][5]+bv1.y, acc[i][6]+bv1.z, acc[i][7]+bv1.w);
    }
}

// ======================= flash attention (fp32, Br=Bc=64) =======================
// grid: (T/64, B*H). smem: Qs[e][r] 16KB, Ks[e][c] 16KB, Vs[c][d] 16KB, Ps[r][68] 17KB
__global__ void __launch_bounds__(256) attn_kernel()
{
    extern __shared__ float sm[];
    float* Qs = sm;            // transposed [e*64 + r]
    float* Ks = sm + 4096;     // transposed [e*64 + c]
    float* Vs = sm + 8192;     // natural    [c*64 + d]
    float* Ps = sm + 12288;    // padded     [r*68 + c]
    const int tid = threadIdx.x;
    const int tx = tid & 15, ty = tid >> 4;
    const int t0 = blockIdx.x << 6;
    const int bh = blockIdx.y;
    const float* qp = g_q + (size_t)bh * (Tn*HDn);
    const float* kp = g_k + (size_t)bh * (Tn*HDn);
    const float* vp = g_v + (size_t)bh * (Tn*HDn);

    #pragma unroll
    for (int rep = 0; rep < 4; rep++) {
        int fi = tid + rep*256;
        int r = fi >> 4;
        int e = (fi & 15) << 2;
        float4 v = *(const float4*)(qp + (t0 + r)*HDn + e);
        Qs[(e+0)*64 + r] = v.x*0.125f;
        Qs[(e+1)*64 + r] = v.y*0.125f;
        Qs[(e+2)*64 + r] = v.z*0.125f;
        Qs[(e+3)*64 + r] = v.w*0.125f;
    }

    float m_i[4], l_i[4], acc[4][4];
    #pragma unroll
    for (int i = 0; i < 4; i++) {
        m_i[i] = -1e30f; l_i[i] = 0.f;
        #pragma unroll
        for (int j = 0; j < 4; j++) acc[i][j] = 0.f;
    }

    for (int kb = 0; kb < Tn; kb += 64) {
        __syncthreads();   // prior iter done with Ks/Vs/Ps; also fences Qs on iter 0
        #pragma unroll
        for (int rep = 0; rep < 4; rep++) {
            int fi = tid + rep*256;
            int r = fi >> 4;
            int e = (fi & 15) << 2;
            float4 kv = *(const float4*)(kp + (kb + r)*HDn + e);
            Ks[(e+0)*64 + r] = kv.x;
            Ks[(e+1)*64 + r] = kv.y;
            Ks[(e+2)*64 + r] = kv.z;
            Ks[(e+3)*64 + r] = kv.w;
            float4 vv = *(const float4*)(vp + (kb + r)*HDn + e);
            *(float4*)&Vs[r*64 + e] = vv;
        }
        __syncthreads();

        float s[4][4];
        #pragma unroll
        for (int i = 0; i < 4; i++)
            #pragma unroll
            for (int j = 0; j < 4; j++) s[i][j] = 0.f;
        #pragma unroll
        for (int e = 0; e < 64; e++) {
            float4 q4 = *(const float4*)&Qs[e*64 + (ty<<2)];
            float4 k4 = *(const float4*)&Ks[e*64 + (tx<<2)];
            float qa[4] = {q4.x,q4.y,q4.z,q4.w};
            float ka4[4] = {k4.x,k4.y,k4.z,k4.w};
            #pragma unroll
            for (int i = 0; i < 4; i++)
                #pragma unroll
                for (int j = 0; j < 4; j++) s[i][j] += qa[i]*ka4[j];
        }

        #pragma unroll
        for (int i = 0; i < 4; i++) {
            float mx = fmaxf(fmaxf(s[i][0], s[i][1]), fmaxf(s[i][2], s[i][3]));
            mx = fmaxf(mx, __shfl_xor_sync(0xffffffffu, mx, 1));
            mx = fmaxf(mx, __shfl_xor_sync(0xffffffffu, mx, 2));
            mx = fmaxf(mx, __shfl_xor_sync(0xffffffffu, mx, 4));
            mx = fmaxf(mx, __shfl_xor_sync(0xffffffffu, mx, 8));
            float mn = fmaxf(m_i[i], mx);
            float alpha = __expf(m_i[i] - mn);
            m_i[i] = mn;
            float rs = 0.f;
            #pragma unroll
            for (int j = 0; j < 4; j++) { s[i][j] = __expf(s[i][j] - mn); rs += s[i][j]; }
            rs += __shfl_xor_sync(0xffffffffu, rs, 1);
            rs += __shfl_xor_sync(0xffffffffu, rs, 2);
            rs += __shfl_xor_sync(0xffffffffu, rs, 4);
            rs += __shfl_xor_sync(0xffffffffu, rs, 8);
            l_i[i] = l_i[i]*alpha + rs;
            #pragma unroll
            for (int j = 0; j < 4; j++) acc[i][j] *= alpha;
            *(float4*)&Ps[((ty<<2)+i)*68 + (tx<<2)] = make_float4(s[i][0], s[i][1], s[i][2], s[i][3]);
        }
        __syncthreads();

        // PV: process 4 columns per step, vectorized P loads (8 LDS.128 / 64 FFMA)
        #pragma unroll
        for (int c = 0; c < 64; c += 4) {
            float4 v0 = *(const float4*)&Vs[(c+0)*64 + (tx<<2)];
            float4 v1 = *(const float4*)&Vs[(c+1)*64 + (tx<<2)];
            float4 v2 = *(const float4*)&Vs[(c+2)*64 + (tx<<2)];
            float4 v3 = *(const float4*)&Vs[(c+3)*64 + (tx<<2)];
            #pragma unroll
            for (int i = 0; i < 4; i++) {
                float4 p4 = *(const float4*)&Ps[((ty<<2)+i)*68 + c];
                acc[i][0] += p4.x*v0.x; acc[i][1] += p4.x*v0.y; acc[i][2] += p4.x*v0.z; acc[i][3] += p4.x*v0.w;
                acc[i][0] += p4.y*v1.x; acc[i][1] += p4.y*v1.y; acc[i][2] += p4.y*v1.z; acc[i][3] += p4.y*v1.w;
                acc[i][0] += p4.z*v2.x; acc[i][1] += p4.z*v2.y; acc[i][2] += p4.z*v2.z; acc[i][3] += p4.z*v2.w;
                acc[i][0] += p4.w*v3.x; acc[i][1] += p4.w*v3.y; acc[i][2] += p4.w*v3.z; acc[i][3] += p4.w*v3.w;
            }
        }
    }

    const int b = bh >> 4, h = bh & 15;
    #pragma unroll
    for (int i = 0; i < 4; i++) {
        float inv = 1.0f / l_i[i];
        int t = t0 + (ty<<2) + i;
        float4 o = make_float4(acc[i][0]*inv, acc[i][1]*inv, acc[i][2]*inv, acc[i][3]*inv);
        *(float4*)&g_ctx[((size_t)(b*Tn + t))*Dn + h*HDn + (tx<<2)] = o;
    }
}

// ======================= launch =======================
extern "C" void kernel_launch(void* const* d_in, const int* in_sizes, int n_in,
                              void* d_out, int out_size)
{
    const float* x    = (const float*)d_in[0];
    const float* ln1g = (const float*)d_in[1];
    const float* ln1b = (const float*)d_in[2];
    const float* ln2g = (const float*)d_in[3];
    const float* ln2b = (const float*)d_in[4];
    const float* Wq   = (const float*)d_in[5];
    const float* bq   = (const float*)d_in[6];
    const float* Wk   = (const float*)d_in[7];
    const float* bk   = (const float*)d_in[8];
    const float* Wv   = (const float*)d_in[9];
    const float* bv   = (const float*)d_in[10];
    const float* Wo   = (const float*)d_in[11];
    const float* bo   = (const float*)d_in[12];
    const float* W1   = (const float*)d_in[13];
    const float* b1   = (const float*)d_in[14];
    const float* W2   = (const float*)d_in[15];
    const float* b2   = (const float*)d_in[16];
    float* out = (float*)d_out;

    float *p_h, *p_x1, *p_h2, *p_ctx, *p_ff;
    cudaGetSymbolAddress((void**)&p_h,   g_h);
    cudaGetSymbolAddress((void**)&p_x1,  g_x1);
    cudaGetSymbolAddress((void**)&p_h2,  g_h2);
    cudaGetSymbolAddress((void**)&p_ctx, g_ctx);
    cudaGetSymbolAddress((void**)&p_ff,  g_ff);

    cudaFuncSetAttribute(attn_kernel, cudaFuncAttributeMaxDynamicSharedMemorySize, 66560);

    // h = LN1(x)
    ln_kernel<<<BT, 256>>>(x, ln1g, ln1b, p_h);
    // q,k,v = h @ W{q,k,v} + b  (per head), one fused launch
    qkv128_kernel<<<dim3(24, BT/128), 256>>>(Wq, Wk, Wv, bq, bk, bv);
    // ctx = softmax(q k^T / 8) v   -> (b,t,h*64+e)
    attn_kernel<<<dim3(Tn/64, Bn*Hn), 256, 66560>>>();
    // x1 = x + ctx @ Wo + bo
    sgemm128_kernel<<<dim3(Dn/128, BT/128), 256>>>(p_ctx, Wo, bo, x, p_x1, BT, Dn, Dn, 0);
    // h2 = LN2(x1)
    ln_kernel<<<BT, 256>>>(p_x1, ln2g, ln2b, p_h2);
    // ff = gelu(h2 @ W1 + b1)
    sgemm128_kernel<<<dim3(FFn/128, BT/128), 256>>>(p_h2, W1, b1, nullptr, p_ff, BT, FFn, Dn, 1);
    // out = x1 + ff @ W2 + b2
    sgemm128_kernel<<<dim3(Dn/128, BT/128), 256>>>(p_ff, W2, b2, p_x1, out, BT, Dn, FFn, 0);
}

// round 10
// speedup vs baseline: 1.1356x; 1.0219x over previous
#include <cuda_runtime.h>
#include <math.h>

#define Bn  8
#define Tn  1024
#define Dn  1024
#define Hn  16
#define HDn 64
#define FFn 4096
#define BT  (Bn*Tn)

typedef unsigned long long ull;

// packed 2xfp32 FMA (FFMA2) — ptxas never emits this from C++; PTX only.
#define FFMA2(d, a, b, c) \
    asm("fma.rn.f32x2 %0, %1, %2, %3;" : "=l"(d) : "l"(a), "l"(b), "l"(c))
#define PACK2(out, lo, hi) \
    asm("mov.b64 %0, {%1, %2};" : "=l"(out) : "r"(lo), "r"(hi))
#define UNPACK2(lo, hi, in) \
    asm("mov.b64 {%0, %1}, %2;" : "=r"(lo), "=r"(hi) : "l"(in))

// ---- scratch (static device globals; no allocation anywhere) ----
__device__ float g_h  [BT*Dn];        // LN1 output
__device__ float g_q  [Bn*Hn*Tn*HDn];
__device__ float g_k  [Bn*Hn*Tn*HDn];
__device__ float g_v  [Bn*Hn*Tn*HDn];
__device__ float g_ctx[BT*Dn];        // attention context, (b,t,h*64+e)
__device__ float g_x1 [BT*Dn];        // x + attn_out
__device__ float g_h2 [BT*Dn];        // LN2 output
__device__ float g_ff [BT*FFn];       // gelu(h2@W1+b1)

// ======================= LayerNorm =======================
__global__ void __launch_bounds__(256) ln_kernel(const float* __restrict__ x,
                                                 const float* __restrict__ gma,
                                                 const float* __restrict__ bta,
                                                 float* __restrict__ out)
{
    int row = blockIdx.x;
    int tid = threadIdx.x;
    const float4 v = *(const float4*)(x + row*Dn + tid*4);
    float s = v.x + v.y + v.z + v.w;
    float q = v.x*v.x + v.y*v.y + v.z*v.z + v.w*v.w;
    #pragma unroll
    for (int o = 16; o > 0; o >>= 1) {
        s += __shfl_xor_sync(0xffffffffu, s, o);
        q += __shfl_xor_sync(0xffffffffu, q, o);
    }
    __shared__ float ss[8], sq[8];
    __shared__ float s_mu, s_rs;
    int w = tid >> 5;
    if ((tid & 31) == 0) { ss[w] = s; sq[w] = q; }
    __syncthreads();
    if (tid == 0) {
        float ts = 0.f, tq = 0.f;
        #pragma unroll
        for (int i = 0; i < 8; i++) { ts += ss[i]; tq += sq[i]; }
        float mu  = ts * (1.0f/Dn);
        float var = tq * (1.0f/Dn) - mu*mu;
        s_mu = mu;
        s_rs = rsqrtf(var + 1e-5f);
    }
    __syncthreads();
    float mu = s_mu, rs = s_rs;
    const float4 g4 = *(const float4*)(gma + tid*4);
    const float4 b4 = *(const float4*)(bta + tid*4);
    float4 o;
    o.x = (v.x - mu)*rs*g4.x + b4.x;
    o.y = (v.y - mu)*rs*g4.y + b4.y;
    o.z = (v.z - mu)*rs*g4.z + b4.z;
    o.w = (v.w - mu)*rs*g4.w + b4.w;
    *(float4*)(out + row*Dn + tid*4) = o;
}

// ---- shared FFMA2 microkernel: 8x8 per-thread outer product, packed pairs ----
// accP[i][j2] holds (acc[i][2*j2], acc[i][2*j2+1])
__device__ __forceinline__ void mk_ffma2_8x8(
    ull accP[8][4], const float av[8], const float bv[8])
{
    ull bp[4], ap[8];
    #pragma unroll
    for (int j2 = 0; j2 < 4; j2++)
        PACK2(bp[j2], __float_as_uint(bv[2*j2]), __float_as_uint(bv[2*j2+1]));
    #pragma unroll
    for (int i = 0; i < 8; i++) {
        unsigned int au = __float_as_uint(av[i]);
        PACK2(ap[i], au, au);
    }
    #pragma unroll
    for (int i = 0; i < 8; i++)
        #pragma unroll
        for (int j2 = 0; j2 < 4; j2++)
            FFMA2(accP[i][j2], ap[i], bp[j2], accP[i][j2]);
}

// ======================= SGEMM 128x128, BK=8, 8x8/thread, double-buffered, FFMA2 =======================
// C[M,N] = A[M,K] @ B[K,N] + bias ; optional exact GELU ; optional +res
__global__ void __launch_bounds__(256, 2) sgemm128_kernel(
    const float* __restrict__ A, const float* __restrict__ Bm,
    const float* __restrict__ bias, const float* __restrict__ res,
    float* __restrict__ C, int M, int N, int K, int gelu)
{
    __shared__ float As[2][8][132];   // transposed [k][row], pitch 132 (conflict-free stores)
    __shared__ float Bs[2][8][128];   // natural    [k][col]
    const int tid = threadIdx.x;
    const int tx = tid & 15, ty = tid >> 4;
    const int row0 = blockIdx.y << 7;
    const int col0 = blockIdx.x << 7;
    const int a_row = tid >> 1, a_k = (tid & 1) << 2;
    const int b_row = tid >> 5, b_col = (tid & 31) << 2;

    const float* Ap = A + (row0 + a_row) * K + a_k;
    const float* Bp = Bm + b_row * N + col0 + b_col;

    ull accP[8][4];
    #pragma unroll
    for (int i = 0; i < 8; i++)
        #pragma unroll
        for (int j = 0; j < 4; j++) accP[i][j] = 0ull;   // (0.0f, 0.0f)

    // prologue: tile 0
    {
        float4 a = *(const float4*)(Ap);
        float4 b = *(const float4*)(Bp);
        As[0][a_k+0][a_row] = a.x; As[0][a_k+1][a_row] = a.y;
        As[0][a_k+2][a_row] = a.z; As[0][a_k+3][a_row] = a.w;
        *(float4*)&Bs[0][b_row][b_col] = b;
    }
    __syncthreads();

    const int ntiles = K >> 3;
    for (int t = 0; t < ntiles; t++) {
        const int cur = t & 1;
        float4 an, bn;
        const bool more = (t + 1 < ntiles);
        if (more) {
            an = *(const float4*)(Ap + (t+1)*8);
            bn = *(const float4*)(Bp + (size_t)(t+1)*8*N);
        }
        #pragma unroll
        for (int kk = 0; kk < 8; kk++) {
            float4 a0 = *(const float4*)&As[cur][kk][ty*8];
            float4 a1 = *(const float4*)&As[cur][kk][ty*8 + 4];
            float4 b0 = *(const float4*)&Bs[cur][kk][tx*8];
            float4 b1 = *(const float4*)&Bs[cur][kk][tx*8 + 4];
            float av[8] = {a0.x,a0.y,a0.z,a0.w,a1.x,a1.y,a1.z,a1.w};
            float bv[8] = {b0.x,b0.y,b0.z,b0.w,b1.x,b1.y,b1.z,b1.w};
            mk_ffma2_8x8(accP, av, bv);
        }
        if (more) {
            const int nxt = cur ^ 1;
            As[nxt][a_k+0][a_row] = an.x; As[nxt][a_k+1][a_row] = an.y;
            As[nxt][a_k+2][a_row] = an.z; As[nxt][a_k+3][a_row] = an.w;
            *(float4*)&Bs[nxt][b_row][b_col] = bn;
            __syncthreads();
        }
    }

    const int cc = col0 + (tx << 3);
    const float4 bv0 = *(const float4*)(bias + cc);
    const float4 bv1 = *(const float4*)(bias + cc + 4);
    const float bb[8] = {bv0.x,bv0.y,bv0.z,bv0.w,bv1.x,bv1.y,bv1.z,bv1.w};
    #pragma unroll
    for (int i = 0; i < 8; i++) {
        const int r = row0 + ty*8 + i;
        float o[8];
        #pragma unroll
        for (int j2 = 0; j2 < 4; j2++) {
            unsigned int lo, hi;
            UNPACK2(lo, hi, accP[i][j2]);
            o[2*j2]   = __uint_as_float(lo) + bb[2*j2];
            o[2*j2+1] = __uint_as_float(hi) + bb[2*j2+1];
        }
        if (gelu) {
            #pragma unroll
            for (int j = 0; j < 8; j++)
                o[j] = 0.5f*o[j]*(1.0f + erff(o[j]*0.70710678118654752f));
        }
        if (res) {
            float4 r0 = *(const float4*)(res + (size_t)r*N + cc);
            float4 r1 = *(const float4*)(res + (size_t)r*N + cc + 4);
            o[0]+=r0.x; o[1]+=r0.y; o[2]+=r0.z; o[3]+=r0.w;
            o[4]+=r1.x; o[5]+=r1.y; o[6]+=r1.z; o[7]+=r1.w;
        }
        *(float4*)(C + (size_t)r*N + cc)     = make_float4(o[0],o[1],o[2],o[3]);
        *(float4*)(C + (size_t)r*N + cc + 4) = make_float4(o[4],o[5],o[6],o[7]);
    }
}

// ======================= fused QKV projection (128x128 tiles, head-blocked B, FFMA2) =======================
// grid.x = 24: proj = bx>>3, col-tile = bx&7. grid.y = 64 row tiles.
__global__ void __launch_bounds__(256, 2) qkv128_kernel(
    const float* __restrict__ Wq, const float* __restrict__ Wk, const float* __restrict__ Wv,
    const float* __restrict__ bq, const float* __restrict__ bk, const float* __restrict__ bv)
{
    __shared__ float As[2][8][132];
    __shared__ float Bs[2][8][128];
    const int proj = blockIdx.x >> 3;
    const int col0 = (blockIdx.x & 7) << 7;          // proj-local column tile
    const float* W    = (proj == 0 ? Wq : (proj == 1 ? Wk : Wv));
    const float* bias = (proj == 0 ? bq : (proj == 1 ? bk : bv));
    float* outp       = (proj == 0 ? g_q : (proj == 1 ? g_k : g_v));

    const int tid = threadIdx.x;
    const int tx = tid & 15, ty = tid >> 4;
    const int row0 = blockIdx.y << 7;
    const int a_row = tid >> 1, a_k = (tid & 1) << 2;
    const int b_row = tid >> 5, b_col = (tid & 31) << 2;

    // virtual B[d, c] with c = col0 + b_col -> W[h, d, e], h=c>>6, e=c&63
    const int gcol = col0 + b_col;
    const float* Ap = g_h + (row0 + a_row) * Dn + a_k;
    const float* Bp = W + (gcol >> 6) * (Dn*HDn) + b_row * HDn + (gcol & 63);

    ull accP[8][4];
    #pragma unroll
    for (int i = 0; i < 8; i++)
        #pragma unroll
        for (int j = 0; j < 4; j++) accP[i][j] = 0ull;

    {
        float4 a = *(const float4*)(Ap);
        float4 b = *(const float4*)(Bp);
        As[0][a_k+0][a_row] = a.x; As[0][a_k+1][a_row] = a.y;
        As[0][a_k+2][a_row] = a.z; As[0][a_k+3][a_row] = a.w;
        *(float4*)&Bs[0][b_row][b_col] = b;
    }
    __syncthreads();

    const int ntiles = Dn >> 3;   // 128
    for (int t = 0; t < ntiles; t++) {
        const int cur = t & 1;
        float4 an, bn;
        const bool more = (t + 1 < ntiles);
        if (more) {
            an = *(const float4*)(Ap + (t+1)*8);
            bn = *(const float4*)(Bp + (t+1)*8*HDn);
        }
        #pragma unroll
        for (int kk = 0; kk < 8; kk++) {
            float4 a0 = *(const float4*)&As[cur][kk][ty*8];
            float4 a1 = *(const float4*)&As[cur][kk][ty*8 + 4];
            float4 b0 = *(const float4*)&Bs[cur][kk][tx*8];
            float4 b1 = *(const float4*)&Bs[cur][kk][tx*8 + 4];
            float av[8] = {a0.x,a0.y,a0.z,a0.w,a1.x,a1.y,a1.z,a1.w};
            float bv2[8] = {b0.x,b0.y,b0.z,b0.w,b1.x,b1.y,b1.z,b1.w};
            mk_ffma2_8x8(accP, av, bv2);
        }
        if (more) {
            const int nxt = cur ^ 1;
            As[nxt][a_k+0][a_row] = an.x; As[nxt][a_k+1][a_row] = an.y;
            As[nxt][a_k+2][a_row] = an.z; As[nxt][a_k+3][a_row] = an.w;
            *(float4*)&Bs[nxt][b_row][b_col] = bn;
            __syncthreads();
        }
    }

    // epilogue: cols c = col0 + tx*8 .. +7, all within one head
    const int c = col0 + (tx << 3);
    const int h = c >> 6, e = c & 63;
    const float4 bv0 = *(const float4*)(bias + c);       // bias is contiguous (H,HD) = 1024 floats
    const float4 bv1 = *(const float4*)(bias + c + 4);
    const float bb[8] = {bv0.x,bv0.y,bv0.z,bv0.w,bv1.x,bv1.y,bv1.z,bv1.w};
    #pragma unroll
    for (int i = 0; i < 8; i++) {
        const int r = row0 + ty*8 + i;
        const int b = r >> 10, tt = r & 1023;
        float o[8];
        #pragma unroll
        for (int j2 = 0; j2 < 4; j2++) {
            unsigned int lo, hi;
            UNPACK2(lo, hi, accP[i][j2]);
            o[2*j2]   = __uint_as_float(lo) + bb[2*j2];
            o[2*j2+1] = __uint_as_float(hi) + bb[2*j2+1];
        }
        float* op = outp + (((size_t)(b*Hn + h)*Tn + tt)*HDn + e);
        *(float4*)(op)     = make_float4(o[0],o[1],o[2],o[3]);
        *(float4*)(op + 4) = make_float4(o[4],o[5],o[6],o[7]);
    }
}

// ======================= flash attention (fp32, Br=Bc=64) =======================
// grid: (T/64, B*H). smem: Qs[e][r] 16KB, Ks[e][c] 16KB, Vs[c][d] 16KB, Ps[r][68] 17KB
__global__ void __launch_bounds__(256) attn_kernel()
{
    extern __shared__ float sm[];
    float* Qs = sm;            // transposed [e*64 + r]
    float* Ks = sm + 4096;     // transposed [e*64 + c]
    float* Vs = sm + 8192;     // natural    [c*64 + d]
    float* Ps = sm + 12288;    // padded     [r*68 + c]
    const int tid = threadIdx.x;
    const int tx = tid & 15, ty = tid >> 4;
    const int t0 = blockIdx.x << 6;
    const int bh = blockIdx.y;
    const float* qp = g_q + (size_t)bh * (Tn*HDn);
    const float* kp = g_k + (size_t)bh * (Tn*HDn);
    const float* vp = g_v + (size_t)bh * (Tn*HDn);

    #pragma unroll
    for (int rep = 0; rep < 4; rep++) {
        int fi = tid + rep*256;
        int r = fi >> 4;
        int e = (fi & 15) << 2;
        float4 v = *(const float4*)(qp + (t0 + r)*HDn + e);
        Qs[(e+0)*64 + r] = v.x*0.125f;
        Qs[(e+1)*64 + r] = v.y*0.125f;
        Qs[(e+2)*64 + r] = v.z*0.125f;
        Qs[(e+3)*64 + r] = v.w*0.125f;
    }

    float m_i[4], l_i[4], acc[4][4];
    #pragma unroll
    for (int i = 0; i < 4; i++) {
        m_i[i] = -1e30f; l_i[i] = 0.f;
        #pragma unroll
        for (int j = 0; j < 4; j++) acc[i][j] = 0.f;
    }

    for (int kb = 0; kb < Tn; kb += 64) {
        __syncthreads();   // prior iter done with Ks/Vs/Ps; also fences Qs on iter 0
        #pragma unroll
        for (int rep = 0; rep < 4; rep++) {
            int fi = tid + rep*256;
            int r = fi >> 4;
            int e = (fi & 15) << 2;
            float4 kv = *(const float4*)(kp + (kb + r)*HDn + e);
            Ks[(e+0)*64 + r] = kv.x;
            Ks[(e+1)*64 + r] = kv.y;
            Ks[(e+2)*64 + r] = kv.z;
            Ks[(e+3)*64 + r] = kv.w;
            float4 vv = *(const float4*)(vp + (kb + r)*HDn + e);
            *(float4*)&Vs[r*64 + e] = vv;
        }
        __syncthreads();

        float s[4][4];
        #pragma unroll
        for (int i = 0; i < 4; i++)
            #pragma unroll
            for (int j = 0; j < 4; j++) s[i][j] = 0.f;
        #pragma unroll
        for (int e = 0; e < 64; e++) {
            float4 q4 = *(const float4*)&Qs[e*64 + (ty<<2)];
            float4 k4 = *(const float4*)&Ks[e*64 + (tx<<2)];
            float qa[4] = {q4.x,q4.y,q4.z,q4.w};
            float ka4[4] = {k4.x,k4.y,k4.z,k4.w};
            #pragma unroll
            for (int i = 0; i < 4; i++)
                #pragma unroll
                for (int j = 0; j < 4; j++) s[i][j] += qa[i]*ka4[j];
        }

        #pragma unroll
        for (int i = 0; i < 4; i++) {
            float mx = fmaxf(fmaxf(s[i][0], s[i][1]), fmaxf(s[i][2], s[i][3]));
            mx = fmaxf(mx, __shfl_xor_sync(0xffffffffu, mx, 1));
            mx = fmaxf(mx, __shfl_xor_sync(0xffffffffu, mx, 2));
            mx = fmaxf(mx, __shfl_xor_sync(0xffffffffu, mx, 4));
            mx = fmaxf(mx, __shfl_xor_sync(0xffffffffu, mx, 8));
            float mn = fmaxf(m_i[i], mx);
            float alpha = __expf(m_i[i] - mn);
            m_i[i] = mn;
            float rs = 0.f;
            #pragma unroll
            for (int j = 0; j < 4; j++) { s[i][j] = __expf(s[i][j] - mn); rs += s[i][j]; }
            rs += __shfl_xor_sync(0xffffffffu, rs, 1);
            rs += __shfl_xor_sync(0xffffffffu, rs, 2);
            rs += __shfl_xor_sync(0xffffffffu, rs, 4);
            rs += __shfl_xor_sync(0xffffffffu, rs, 8);
            l_i[i] = l_i[i]*alpha + rs;
            #pragma unroll
            for (int j = 0; j < 4; j++) acc[i][j] *= alpha;
            *(float4*)&Ps[((ty<<2)+i)*68 + (tx<<2)] = make_float4(s[i][0], s[i][1], s[i][2], s[i][3]);
        }
        __syncthreads();

        // PV: process 4 columns per step, vectorized P loads (8 LDS.128 / 64 FFMA)
        #pragma unroll
        for (int c = 0; c < 64; c += 4) {
            float4 v0 = *(const float4*)&Vs[(c+0)*64 + (tx<<2)];
            float4 v1 = *(const float4*)&Vs[(c+1)*64 + (tx<<2)];
            float4 v2 = *(const float4*)&Vs[(c+2)*64 + (tx<<2)];
            float4 v3 = *(const float4*)&Vs[(c+3)*64 + (tx<<2)];
            #pragma unroll
            for (int i = 0; i < 4; i++) {
                float4 p4 = *(const float4*)&Ps[((ty<<2)+i)*68 + c];
                acc[i][0] += p4.x*v0.x; acc[i][1] += p4.x*v0.y; acc[i][2] += p4.x*v0.z; acc[i][3] += p4.x*v0.w;
                acc[i][0] += p4.y*v1.x; acc[i][1] += p4.y*v1.y; acc[i][2] += p4.y*v1.z; acc[i][3] += p4.y*v1.w;
                acc[i][0] += p4.z*v2.x; acc[i][1] += p4.z*v2.y; acc[i][2] += p4.z*v2.z; acc[i][3] += p4.z*v2.w;
                acc[i][0] += p4.w*v3.x; acc[i][1] += p4.w*v3.y; acc[i][2] += p4.w*v3.z; acc[i][3] += p4.w*v3.w;
            }
        }
    }

    const int b = bh >> 4, h = bh & 15;
    #pragma unroll
    for (int i = 0; i < 4; i++) {
        float inv = 1.0f / l_i[i];
        int t = t0 + (ty<<2) + i;
        float4 o = make_float4(acc[i][0]*inv, acc[i][1]*inv, acc[i][2]*inv, acc[i][3]*inv);
        *(float4*)&g_ctx[((size_t)(b*Tn + t))*Dn + h*HDn + (tx<<2)] = o;
    }
}

// ======================= launch =======================
extern "C" void kernel_launch(void* const* d_in, const int* in_sizes, int n_in,
                              void* d_out, int out_size)
{
    const float* x    = (const float*)d_in[0];
    const float* ln1g = (const float*)d_in[1];
    const float* ln1b = (const float*)d_in[2];
    const float* ln2g = (const float*)d_in[3];
    const float* ln2b = (const float*)d_in[4];
    const float* Wq   = (const float*)d_in[5];
    const float* bq   = (const float*)d_in[6];
    const float* Wk   = (const float*)d_in[7];
    const float* bk   = (const float*)d_in[8];
    const float* Wv   = (const float*)d_in[9];
    const float* bv   = (const float*)d_in[10];
    const float* Wo   = (const float*)d_in[11];
    const float* bo   = (const float*)d_in[12];
    const float* W1   = (const float*)d_in[13];
    const float* b1   = (const float*)d_in[14];
    const float* W2   = (const float*)d_in[15];
    const float* b2   = (const float*)d_in[16];
    float* out = (float*)d_out;

    float *p_h, *p_x1, *p_h2, *p_ctx, *p_ff;
    cudaGetSymbolAddress((void**)&p_h,   g_h);
    cudaGetSymbolAddress((void**)&p_x1,  g_x1);
    cudaGetSymbolAddress((void**)&p_h2,  g_h2);
    cudaGetSymbolAddress((void**)&p_ctx, g_ctx);
    cudaGetSymbolAddress((void**)&p_ff,  g_ff);

    cudaFuncSetAttribute(attn_kernel, cudaFuncAttributeMaxDynamicSharedMemorySize, 66560);

    // h = LN1(x)
    ln_kernel<<<BT, 256>>>(x, ln1g, ln1b, p_h);
    // q,k,v = h @ W{q,k,v} + b  (per head), one fused launch
    qkv128_kernel<<<dim3(24, BT/128), 256>>>(Wq, Wk, Wv, bq, bk, bv);
    // ctx = softmax(q k^T / 8) v   -> (b,t,h*64+e)
    attn_kernel<<<dim3(Tn/64, Bn*Hn), 256, 66560>>>();
    // x1 = x + ctx @ Wo + bo
    sgemm128_kernel<<<dim3(Dn/128, BT/128), 256>>>(p_ctx, Wo, bo, x, p_x1, BT, Dn, Dn, 0);
    // h2 = LN2(x1)
    ln_kernel<<<BT, 256>>>(p_x1, ln2g, ln2b, p_h2);
    // ff = gelu(h2 @ W1 + b1)
    sgemm128_kernel<<<dim3(FFn/128, BT/128), 256>>>(p_h2, W1, b1, nullptr, p_ff, BT, FFn, Dn, 1);
    // out = x1 + ff @ W2 + b2
    sgemm128_kernel<<<dim3(Dn/128, BT/128), 256>>>(p_ff, W2, b2, p_x1, out, BT, Dn, FFn, 0);
}

// round 15
// speedup vs baseline: 2.0183x; 1.7773x over previous
#include <cuda_runtime.h>
#include <cuda_bf16.h>
#include <math.h>

#define Bn  8
#define Tn  1024
#define Dn  1024
#define Hn  16
#define HDn 64
#define FFn 4096
#define BT  (Bn*Tn)

typedef unsigned short u16;
typedef unsigned int   u32;

// ---- scratch (static device globals; no allocation anywhere) ----
__device__ float g_q  [Bn*Hn*Tn*HDn];
__device__ float g_k  [Bn*Hn*Tn*HDn];
__device__ float g_v  [Bn*Hn*Tn*HDn];
__device__ float g_x1 [BT*Dn];
// bf16 hi/lo split buffers
__device__ u16 g_hh [BT*Dn],  g_hl [BT*Dn];     // LN1 out
__device__ u16 g_ctxh[BT*Dn], g_ctxl[BT*Dn];    // attention ctx
__device__ u16 g_h2h[BT*Dn],  g_h2l[BT*Dn];     // LN2 out
__device__ u16 g_ffh[BT*FFn], g_ffl[BT*FFn];    // gelu(ffn1)
__device__ u16 g_woh[Dn*Dn],   g_wol[Dn*Dn];    // Wo^T [n][k]
__device__ u16 g_w1h[Dn*FFn],  g_w1l[Dn*FFn];   // W1^T
__device__ u16 g_w2h[FFn*Dn],  g_w2l[FFn*Dn];   // W2^T
__device__ u16 g_wqh[3*Dn*Dn], g_wql[3*Dn*Dn];  // QKV weights^T, n = proj*1024+h*64+e

__device__ __forceinline__ void split1(float x, u16& h, u16& l) {
    __nv_bfloat16 hb = __float2bfloat16(x);
    float hf = __bfloat162float(hb);
    __nv_bfloat16 lb = __float2bfloat16(x - hf);
    h = __bfloat16_as_ushort(hb);
    l = __bfloat16_as_ushort(lb);
}

__device__ __forceinline__ u32 smem_u32(const void* p) {
    u32 a;
    asm("{ .reg .u64 t; cvta.to.shared.u64 t, %1; cvt.u32.u64 %0, t; }" : "=r"(a) : "l"(p));
    return a;
}

#define LDSM4(r0,r1,r2,r3,addr) \
    asm volatile("ldmatrix.sync.aligned.m8n8.x4.shared.b16 {%0,%1,%2,%3}, [%4];" \
                 : "=r"(r0),"=r"(r1),"=r"(r2),"=r"(r3) : "r"(addr))
#define LDSM2(r0,r1,addr) \
    asm volatile("ldmatrix.sync.aligned.m8n8.x2.shared.b16 {%0,%1}, [%2];" \
                 : "=r"(r0),"=r"(r1) : "r"(addr))
#define MMA16816(c,a,b) \
    asm volatile("mma.sync.aligned.m16n8k16.row.col.f32.bf16.bf16.f32 " \
                 "{%0,%1,%2,%3}, {%4,%5,%6,%7}, {%8,%9}, {%0,%1,%2,%3};" \
                 : "+f"((c)[0]),"+f"((c)[1]),"+f"((c)[2]),"+f"((c)[3]) \
                 : "r"((a)[0]),"r"((a)[1]),"r"((a)[2]),"r"((a)[3]), "r"((b)[0]),"r"((b)[1]))

// ======================= transpose+split: in[K][N] fp32 -> out[N][K] bf16 hi/lo =======================
__global__ void __launch_bounds__(256) tsplit_kernel(const float* __restrict__ in,
                                                     u16* __restrict__ oh, u16* __restrict__ ol,
                                                     int K, int N)
{
    __shared__ float tile[32][33];
    const int n0 = blockIdx.x << 5, k0 = blockIdx.y << 5;
    const int tx = threadIdx.x, ty = threadIdx.y;   // 32 x 8
    #pragma unroll
    for (int i = 0; i < 32; i += 8)
        tile[ty + i][tx] = in[(size_t)(k0 + ty + i) * N + n0 + tx];
    __syncthreads();
    #pragma unroll
    for (int i = 0; i < 32; i += 8) {
        u16 h, l; split1(tile[tx][ty + i], h, l);
        size_t o = (size_t)(n0 + ty + i) * K + k0 + tx;
        oh[o] = h; ol[o] = l;
    }
}

// QKV weights: W[h][d][e] (per proj) -> g_wq[n][d], n = proj*1024 + h*64 + e
__global__ void __launch_bounds__(256) qkvsplit_kernel(const float* __restrict__ Wq,
                                                       const float* __restrict__ Wk,
                                                       const float* __restrict__ Wv)
{
    __shared__ float tile[32][33];
    const int proj = blockIdx.z >> 4, h = blockIdx.z & 15;
    const float* in = (proj == 0 ? Wq : (proj == 1 ? Wk : Wv)) + (size_t)h * Dn * HDn;
    const int n0 = blockIdx.x << 5, k0 = blockIdx.y << 5;   // n in [0,64), k in [0,1024)
    const int tx = threadIdx.x, ty = threadIdx.y;
    #pragma unroll
    for (int i = 0; i < 32; i += 8)
        tile[ty + i][tx] = in[(size_t)(k0 + ty + i) * HDn + n0 + tx];
    __syncthreads();
    const size_t nb = (size_t)(proj * 1024 + h * 64);
    #pragma unroll
    for (int i = 0; i < 32; i += 8) {
        u16 hh, ll; split1(tile[tx][ty + i], hh, ll);
        size_t o = (nb + n0 + ty + i) * Dn + k0 + tx;
        g_wqh[o] = hh; g_wql[o] = ll;
    }
}

// ======================= LayerNorm -> bf16 hi/lo splits =======================
__global__ void __launch_bounds__(256) ln_split_kernel(const float* __restrict__ x,
                                                       const float* __restrict__ gma,
                                                       const float* __restrict__ bta,
                                                       u16* __restrict__ oh, u16* __restrict__ ol)
{
    int row = blockIdx.x;
    int tid = threadIdx.x;
    const float4 v = *(const float4*)(x + (size_t)row*Dn + tid*4);
    float s = v.x + v.y + v.z + v.w;
    float q = v.x*v.x + v.y*v.y + v.z*v.z + v.w*v.w;
    #pragma unroll
    for (int o = 16; o > 0; o >>= 1) {
        s += __shfl_xor_sync(0xffffffffu, s, o);
        q += __shfl_xor_sync(0xffffffffu, q, o);
    }
    __shared__ float ss[8], sq[8];
    __shared__ float s_mu, s_rs;
    int w = tid >> 5;
    if ((tid & 31) == 0) { ss[w] = s; sq[w] = q; }
    __syncthreads();
    if (tid == 0) {
        float ts = 0.f, tq = 0.f;
        #pragma unroll
        for (int i = 0; i < 8; i++) { ts += ss[i]; tq += sq[i]; }
        float mu  = ts * (1.0f/Dn);
        float var = tq * (1.0f/Dn) - mu*mu;
        s_mu = mu;
        s_rs = rsqrtf(var + 1e-5f);
    }
    __syncthreads();
    float mu = s_mu, rs = s_rs;
    const float4 g4 = *(const float4*)(gma + tid*4);
    const float4 b4 = *(const float4*)(bta + tid*4);
    float o[4];
    o[0] = (v.x - mu)*rs*g4.x + b4.x;
    o[1] = (v.y - mu)*rs*g4.y + b4.y;
    o[2] = (v.z - mu)*rs*g4.z + b4.z;
    o[3] = (v.w - mu)*rs*g4.w + b4.w;
    u16 h[4], l[4];
    #pragma unroll
    for (int j = 0; j < 4; j++) split1(o[j], h[j], l[j]);
    size_t idx = (size_t)row*Dn + tid*4;
    *(uint2*)(oh + idx) = make_uint2((u32)h[0] | ((u32)h[1] << 16), (u32)h[2] | ((u32)h[3] << 16));
    *(uint2*)(ol + idx) = make_uint2((u32)l[0] | ((u32)l[1] << 16), (u32)l[2] | ((u32)l[3] << 16));
}

// ======================= split-bf16 mma.sync GEMM =======================
// C[M,N] = fp32(A) @ fp32(B) + bias, where A = Ah+Al [m][k], B = Bh+Bl [n][k] (both bf16 splits).
// D = Ah*Bh + Ah*Bl + Al*Bh. CTA 128x128, BK=32, 8 warps (warp tile 64x32), m16n8k16.
// mode 0: Cf = acc + bias (+res)         mode 1: (Ch,Cl) = split(gelu(acc + bias))
// mode 2: QKV scatter into g_q/g_k/g_v, bias selected by proj (bias, bias_k, bias_v)
__global__ void __launch_bounds__(256) mma_gemm_kernel(
    const u16* __restrict__ Agh, const u16* __restrict__ Agl,
    const u16* __restrict__ Bgh, const u16* __restrict__ Bgl,
    const float* __restrict__ bias, const float* __restrict__ bias_k, const float* __restrict__ bias_v,
    const float* __restrict__ res, float* __restrict__ Cf,
    u16* __restrict__ Ch, u16* __restrict__ Cl,
    int M, int N, int K, int mode)
{
    __shared__ __align__(16) u16 Ah[128][40];
    __shared__ __align__(16) u16 Al[128][40];
    __shared__ __align__(16) u16 Bh[128][40];
    __shared__ __align__(16) u16 Bl[128][40];

    const int tid = threadIdx.x;
    const int lane = tid & 31, wid = tid >> 5;
    const int warp_m = wid & 1, warp_n = wid >> 1;      // 2 x 4 warp grid
    const int row0 = blockIdx.y << 7;
    const int col0 = blockIdx.x << 7;

    float acc[4][4][4];
    #pragma unroll
    for (int i = 0; i < 4; i++)
        #pragma unroll
        for (int j = 0; j < 4; j++)
            #pragma unroll
            for (int r = 0; r < 4; r++) acc[i][j][r] = 0.f;

    // gmem load mapping: thread -> row tid>>1, 32 bf16 (two 16B chunks at (tid&1)*16)
    const int lr = tid >> 1, lq = (tid & 1) << 4;
    const size_t abase = (size_t)(row0 + lr) * K + lq;
    const size_t bbase = (size_t)(col0 + lr) * K + lq;

    uint4 pAh[2], pAl[2], pBh[2], pBl[2];
    {
        pAh[0] = *(const uint4*)(Agh + abase); pAh[1] = *(const uint4*)(Agh + abase + 8);
        pAl[0] = *(const uint4*)(Agl + abase); pAl[1] = *(const uint4*)(Agl + abase + 8);
        pBh[0] = *(const uint4*)(Bgh + bbase); pBh[1] = *(const uint4*)(Bgh + bbase + 8);
        pBl[0] = *(const uint4*)(Bgl + bbase); pBl[1] = *(const uint4*)(Bgl + bbase + 8);
    }

    const int nk = K >> 5;
    for (int t = 0; t < nk; t++) {
        __syncthreads();   // previous chunk's compute done
        *(uint4*)&Ah[lr][lq]     = pAh[0]; *(uint4*)&Ah[lr][lq + 8] = pAh[1];
        *(uint4*)&Al[lr][lq]     = pAl[0]; *(uint4*)&Al[lr][lq + 8] = pAl[1];
        *(uint4*)&Bh[lr][lq]     = pBh[0]; *(uint4*)&Bh[lr][lq + 8] = pBh[1];
        *(uint4*)&Bl[lr][lq]     = pBl[0]; *(uint4*)&Bl[lr][lq + 8] = pBl[1];
        __syncthreads();
        if (t + 1 < nk) {
            const size_t ko = (size_t)(t + 1) << 5;
            pAh[0] = *(const uint4*)(Agh + abase + ko); pAh[1] = *(const uint4*)(Agh + abase + ko + 8);
            pAl[0] = *(const uint4*)(Agl + abase + ko); pAl[1] = *(const uint4*)(Agl + abase + ko + 8);
            pBh[0] = *(const uint4*)(Bgh + bbase + ko); pBh[1] = *(const uint4*)(Bgh + bbase + ko + 8);
            pBl[0] = *(const uint4*)(Bgl + bbase + ko); pBl[1] = *(const uint4*)(Bgl + bbase + ko + 8);
        }
        #pragma unroll
        for (int s = 0; s < 2; s++) {
            // A frags: ldmatrix x4. lanes0-15: rows0-15@k0, lanes16-31: rows0-15@k8
            u32 aH[4][4], aL[4][4];
            #pragma unroll
            for (int i = 0; i < 4; i++) {
                int arow = warp_m*64 + i*16 + (lane & 15);
                int acol = s*16 + ((lane >> 4) << 3);
                LDSM4(aH[i][0], aH[i][1], aH[i][2], aH[i][3], smem_u32(&Ah[arow][acol]));
                LDSM4(aL[i][0], aL[i][1], aL[i][2], aL[i][3], smem_u32(&Al[arow][acol]));
            }
            // B frags: ldmatrix x2 over [n][k]. lanes0-7: n-rows@k0, 8-15: n-rows@k8
            u32 bH[4][2], bL[4][2];
            #pragma unroll
            for (int j = 0; j < 4; j++) {
                int brow = warp_n*32 + j*8 + (lane & 7);
                int bcol = s*16 + (((lane >> 3) & 1) << 3);
                LDSM2(bH[j][0], bH[j][1], smem_u32(&Bh[brow][bcol]));
                LDSM2(bL[j][0], bL[j][1], smem_u32(&Bl[brow][bcol]));
            }
            #pragma unroll
            for (int i = 0; i < 4; i++)
                #pragma unroll
                for (int j = 0; j < 4; j++) {
                    MMA16816(acc[i][j], aH[i], bH[j]);
                    MMA16816(acc[i][j], aH[i], bL[j]);
                    MMA16816(acc[i][j], aL[i], bH[j]);
                }
        }
    }

    // epilogue: c0,c1 -> (row g, cols 2q,2q+1); c2,c3 -> row g+8
    const int g = lane >> 2, q2 = (lane & 3) << 1;
    #pragma unroll
    for (int i = 0; i < 4; i++) {
        #pragma unroll
        for (int j = 0; j < 4; j++) {
            const int cgl = col0 + warp_n*32 + j*8 + q2;
            #pragma unroll
            for (int half = 0; half < 2; half++) {
                const int r = row0 + warp_m*64 + i*16 + g + half*8;
                float o0 = acc[i][j][half*2 + 0];
                float o1 = acc[i][j][half*2 + 1];
                if (mode == 2) {
                    const int proj = cgl >> 10, cl = cgl & 1023;
                    const float* bp = (proj == 0 ? bias : (proj == 1 ? bias_k : bias_v));
                    o0 += bp[cl]; o1 += bp[cl + 1];
                    const int bb = r >> 10, tt = r & 1023;
                    const int hh = cl >> 6, e = cl & 63;
                    float* op = (proj == 0 ? g_q : (proj == 1 ? g_k : g_v))
                                + (((size_t)(bb*Hn + hh)*Tn + tt)*HDn + e);
                    *(float2*)op = make_float2(o0, o1);
                } else {
                    o0 += bias[cgl]; o1 += bias[cgl + 1];
                    if (mode == 1) {
                        o0 = 0.5f*o0*(1.0f + erff(o0*0.70710678118654752f));
                        o1 = 0.5f*o1*(1.0f + erff(o1*0.70710678118654752f));
                        u16 h0, l0, h1, l1;
                        split1(o0, h0, l0); split1(o1, h1, l1);
                        size_t idx = (size_t)r*N + cgl;
                        *(u32*)(Ch + idx) = (u32)h0 | ((u32)h1 << 16);
                        *(u32*)(Cl + idx) = (u32)l0 | ((u32)l1 << 16);
                    } else {
                        size_t idx = (size_t)r*N + cgl;
                        if (res) {
                            float2 rv = *(const float2*)(res + idx);
                            o0 += rv.x; o1 += rv.y;
                        }
                        *(float2*)(Cf + idx) = make_float2(o0, o1);
                    }
                }
            }
        }
    }
}

// ======================= flash attention (fp32, Br=Bc=64) -> ctx bf16 splits =======================
__global__ void __launch_bounds__(256) attn_kernel()
{
    extern __shared__ float smf[];
    float* Qs = smf;
    float* Ks = smf + 4096;
    float* Vs = smf + 8192;
    float* Ps = smf + 12288;
    const int tid = threadIdx.x;
    const int tx = tid & 15, ty = tid >> 4;
    const int t0 = blockIdx.x << 6;
    const int bh = blockIdx.y;
    const float* qp = g_q + (size_t)bh * (Tn*HDn);
    const float* kp = g_k + (size_t)bh * (Tn*HDn);
    const float* vp = g_v + (size_t)bh * (Tn*HDn);

    #pragma unroll
    for (int rep = 0; rep < 4; rep++) {
        int fi = tid + rep*256;
        int r = fi >> 4;
        int e = (fi & 15) << 2;
        float4 v = *(const float4*)(qp + (t0 + r)*HDn + e);
        Qs[(e+0)*64 + r] = v.x*0.125f;
        Qs[(e+1)*64 + r] = v.y*0.125f;
        Qs[(e+2)*64 + r] = v.z*0.125f;
        Qs[(e+3)*64 + r] = v.w*0.125f;
    }

    float m_i[4], l_i[4], acc[4][4];
    #pragma unroll
    for (int i = 0; i < 4; i++) {
        m_i[i] = -1e30f; l_i[i] = 0.f;
        #pragma unroll
        for (int j = 0; j < 4; j++) acc[i][j] = 0.f;
    }

    for (int kb = 0; kb < Tn; kb += 64) {
        __syncthreads();
        #pragma unroll
        for (int rep = 0; rep < 4; rep++) {
            int fi = tid + rep*256;
            int r = fi >> 4;
            int e = (fi & 15) << 2;
            float4 kv = *(const float4*)(kp + (kb + r)*HDn + e);
            Ks[(e+0)*64 + r] = kv.x;
            Ks[(e+1)*64 + r] = kv.y;
            Ks[(e+2)*64 + r] = kv.z;
            Ks[(e+3)*64 + r] = kv.w;
            float4 vv = *(const float4*)(vp + (kb + r)*HDn + e);
            *(float4*)&Vs[r*64 + e] = vv;
        }
        __syncthreads();

        float s[4][4];
        #pragma unroll
        for (int i = 0; i < 4; i++)
            #pragma unroll
            for (int j = 0; j < 4; j++) s[i][j] = 0.f;
        #pragma unroll
        for (int e = 0; e < 64; e++) {
            float4 q4 = *(const float4*)&Qs[e*64 + (ty<<2)];
            float4 k4 = *(const float4*)&Ks[e*64 + (tx<<2)];
            float qa[4] = {q4.x,q4.y,q4.z,q4.w};
            float ka4[4] = {k4.x,k4.y,k4.z,k4.w};
            #pragma unroll
            for (int i = 0; i < 4; i++)
                #pragma unroll
                for (int j = 0; j < 4; j++) s[i][j] += qa[i]*ka4[j];
        }

        #pragma unroll
        for (int i = 0; i < 4; i++) {
            float mx = fmaxf(fmaxf(s[i][0], s[i][1]), fmaxf(s[i][2], s[i][3]));
            mx = fmaxf(mx, __shfl_xor_sync(0xffffffffu, mx, 1));
            mx = fmaxf(mx, __shfl_xor_sync(0xffffffffu, mx, 2));
            mx = fmaxf(mx, __shfl_xor_sync(0xffffffffu, mx, 4));
            mx = fmaxf(mx, __shfl_xor_sync(0xffffffffu, mx, 8));
            float mn = fmaxf(m_i[i], mx);
            float alpha = __expf(m_i[i] - mn);
            m_i[i] = mn;
            float rs = 0.f;
            #pragma unroll
            for (int j = 0; j < 4; j++) { s[i][j] = __expf(s[i][j] - mn); rs += s[i][j]; }
            rs += __shfl_xor_sync(0xffffffffu, rs, 1);
            rs += __shfl_xor_sync(0xffffffffu, rs, 2);
            rs += __shfl_xor_sync(0xffffffffu, rs, 4);
            rs += __shfl_xor_sync(0xffffffffu, rs, 8);
            l_i[i] = l_i[i]*alpha + rs;
            #pragma unroll
            for (int j = 0; j < 4; j++) acc[i][j] *= alpha;
            *(float4*)&Ps[((ty<<2)+i)*68 + (tx<<2)] = make_float4(s[i][0], s[i][1], s[i][2], s[i][3]);
        }
        __syncthreads();

        #pragma unroll
        for (int c = 0; c < 64; c += 4) {
            float4 v0 = *(const float4*)&Vs[(c+0)*64 + (tx<<2)];
            float4 v1 = *(const float4*)&Vs[(c+1)*64 + (tx<<2)];
            float4 v2 = *(const float4*)&Vs[(c+2)*64 + (tx<<2)];
            float4 v3 = *(const float4*)&Vs[(c+3)*64 + (tx<<2)];
            #pragma unroll
            for (int i = 0; i < 4; i++) {
                float4 p4 = *(const float4*)&Ps[((ty<<2)+i)*68 + c];
                acc[i][0] += p4.x*v0.x; acc[i][1] += p4.x*v0.y; acc[i][2] += p4.x*v0.z; acc[i][3] += p4.x*v0.w;
                acc[i][0] += p4.y*v1.x; acc[i][1] += p4.y*v1.y; acc[i][2] += p4.y*v1.z; acc[i][3] += p4.y*v1.w;
                acc[i][0] += p4.z*v2.x; acc[i][1] += p4.z*v2.y; acc[i][2] += p4.z*v2.z; acc[i][3] += p4.z*v2.w;
                acc[i][0] += p4.w*v3.x; acc[i][1] += p4.w*v3.y; acc[i][2] += p4.w*v3.z; acc[i][3] += p4.w*v3.w;
            }
        }
    }

    const int b = bh >> 4, h = bh & 15;
    #pragma unroll
    for (int i = 0; i < 4; i++) {
        float inv = 1.0f / l_i[i];
        int t = t0 + (ty<<2) + i;
        float o[4] = {acc[i][0]*inv, acc[i][1]*inv, acc[i][2]*inv, acc[i][3]*inv};
        u16 hh[4], ll[4];
        #pragma unroll
        for (int j = 0; j < 4; j++) split1(o[j], hh[j], ll[j]);
        size_t idx = ((size_t)(b*Tn + t))*Dn + h*HDn + (tx<<2);
        *(uint2*)(g_ctxh + idx) = make_uint2((u32)hh[0] | ((u32)hh[1] << 16), (u32)hh[2] | ((u32)hh[3] << 16));
        *(uint2*)(g_ctxl + idx) = make_uint2((u32)ll[0] | ((u32)ll[1] << 16), (u32)ll[2] | ((u32)ll[3] << 16));
    }
}

// ======================= launch =======================
extern "C" void kernel_launch(void* const* d_in, const int* in_sizes, int n_in,
                              void* d_out, int out_size)
{
    const float* x    = (const float*)d_in[0];
    const float* ln1g = (const float*)d_in[1];
    const float* ln1b = (const float*)d_in[2];
    const float* ln2g = (const float*)d_in[3];
    const float* ln2b = (const float*)d_in[4];
    const float* Wq   = (const float*)d_in[5];
    const float* bq   = (const float*)d_in[6];
    const float* Wk   = (const float*)d_in[7];
    const float* bk   = (const float*)d_in[8];
    const float* Wv   = (const float*)d_in[9];
    const float* bv   = (const float*)d_in[10];
    const float* Wo   = (const float*)d_in[11];
    const float* bo   = (const float*)d_in[12];
    const float* W1   = (const float*)d_in[13];
    const float* b1   = (const float*)d_in[14];
    const float* W2   = (const float*)d_in[15];
    const float* b2   = (const float*)d_in[16];
    float* out = (float*)d_out;

    float *p_x1;
    u16 *p_hh, *p_hl, *p_ctxh, *p_ctxl, *p_h2h, *p_h2l, *p_ffh, *p_ffl;
    u16 *p_woh, *p_wol, *p_w1h, *p_w1l, *p_w2h, *p_w2l, *p_wqh, *p_wql;
    cudaGetSymbolAddress((void**)&p_x1,  g_x1);
    cudaGetSymbolAddress((void**)&p_hh,  g_hh);  cudaGetSymbolAddress((void**)&p_hl,  g_hl);
    cudaGetSymbolAddress((void**)&p_ctxh,g_ctxh);cudaGetSymbolAddress((void**)&p_ctxl,g_ctxl);
    cudaGetSymbolAddress((void**)&p_h2h, g_h2h); cudaGetSymbolAddress((void**)&p_h2l, g_h2l);
    cudaGetSymbolAddress((void**)&p_ffh, g_ffh); cudaGetSymbolAddress((void**)&p_ffl, g_ffl);
    cudaGetSymbolAddress((void**)&p_woh, g_woh); cudaGetSymbolAddress((void**)&p_wol, g_wol);
    cudaGetSymbolAddress((void**)&p_w1h, g_w1h); cudaGetSymbolAddress((void**)&p_w1l, g_w1l);
    cudaGetSymbolAddress((void**)&p_w2h, g_w2h); cudaGetSymbolAddress((void**)&p_w2l, g_w2l);
    cudaGetSymbolAddress((void**)&p_wqh, g_wqh); cudaGetSymbolAddress((void**)&p_wql, g_wql);

    cudaFuncSetAttribute(attn_kernel, cudaFuncAttributeMaxDynamicSharedMemorySize, 66560);

    const dim3 tb(32, 8);
    // weight transpose+split
    tsplit_kernel<<<dim3(32, 32),  tb>>>(Wo, p_woh, p_wol, Dn, Dn);
    tsplit_kernel<<<dim3(128, 32), tb>>>(W1, p_w1h, p_w1l, Dn, FFn);
    tsplit_kernel<<<dim3(32, 128), tb>>>(W2, p_w2h, p_w2l, FFn, Dn);
    qkvsplit_kernel<<<dim3(2, 32, 48), tb>>>(Wq, Wk, Wv);
    // h = LN1(x) -> splits
    ln_split_kernel<<<BT, 256>>>(x, ln1g, ln1b, p_hh, p_hl);
    // q,k,v = h @ Wqkv + b   (tensor path, mode 2)
    mma_gemm_kernel<<<dim3(24, 64), 256>>>(p_hh, p_hl, p_wqh, p_wql,
                                           bq, bk, bv, nullptr, nullptr, nullptr, nullptr,
                                           BT, 3*Dn, Dn, 2);
    // attention -> ctx splits
    attn_kernel<<<dim3(Tn/64, Bn*Hn), 256, 66560>>>();
    // x1 = x + ctx @ Wo + bo  (mode 0)
    mma_gemm_kernel<<<dim3(8, 64), 256>>>(p_ctxh, p_ctxl, p_woh, p_wol,
                                          bo, nullptr, nullptr, x, p_x1, nullptr, nullptr,
                                          BT, Dn, Dn, 0);
    // h2 = LN2(x1) -> splits
    ln_split_kernel<<<BT, 256>>>(p_x1, ln2g, ln2b, p_h2h, p_h2l);
    // ff = gelu(h2 @ W1 + b1) -> splits  (mode 1)
    mma_gemm_kernel<<<dim3(32, 64), 256>>>(p_h2h, p_h2l, p_w1h, p_w1l,
                                           b1, nullptr, nullptr, nullptr, nullptr, p_ffh, p_ffl,
                                           BT, FFn, Dn, 1);
    // out = x1 + ff @ W2 + b2  (mode 0)
    mma_gemm_kernel<<<dim3(8, 64), 256>>>(p_ffh, p_ffl, p_w2h, p_w2l,
                                          b2, nullptr, nullptr, p_x1, out, nullptr, nullptr,
                                          BT, Dn, FFn, 0);
}